// round 7
// baseline (speedup 1.0000x reference)
#include <cuda_runtime.h>
#include <cuda_fp16.h>
#include <math.h>

#define NN 40000
#define NE 640000
#define ET 680000       // NE + NN self loops
#define C  128
#define NG 64
#define OC 16
#define EPS 1e-16f

// ---------------- scratch (device globals; no allocation allowed) ----------------
__device__ __half2  g_hh [(size_t)NN * 64];   // H in fp16 (64 half2 per row)
__device__ float    g_t1 [(size_t)NN * C];
__device__ float    g_t2 [(size_t)NN * C];
__device__ float    g_s  [NN];
__device__ float    g_alpha[ET];
__device__ float    g_dinv[NN];
__device__ int      g_hist [NN];
__device__ int      g_hist2[NN];
__device__ int      g_rp  [NN + 1];
__device__ int      g_rp2 [NN + 1];
__device__ int      g_cur [NN];
__device__ int      g_cur2[NN];
__device__ int      g_cse [ET];   // dst-CSR: src node per slot
__device__ int2     g_cde [ET];   // src-CSR: {dst node, dst-CSR slot}
__device__ int      g_bsum [64];
__device__ int      g_bsum2[64];
__device__ float    g_pool[NG * C];
__device__ float    g_cnt [NG];
__device__ float    g_wfrag[3 * 2 * 16384];  // [mat][hi/lo][16384] frag-ordered tf32

// grid-barrier state (per fused kernel: 0=setup, 1=edge, 2=tail)
__device__ int g_barc[4];
__device__ int g_barg[4];

// All blocks of the calling kernel are guaranteed co-resident (grid <= residency).
__device__ __forceinline__ void gbar(int slot, int nb) {
    __syncthreads();
    if (threadIdx.x == 0) {
        volatile int* vgen = &g_barg[slot];
        int g = *vgen;
        __threadfence();
        if (atomicAdd(&g_barc[slot], 1) == nb - 1) {
            g_barc[slot] = 0;
            __threadfence();
            *vgen = g + 1;
        } else {
            while (*vgen == g) __nanosleep(32);
        }
        __threadfence();
    }
    __syncthreads();
}

// ---------------- tf32 helpers ----------------
__device__ __forceinline__ unsigned f2tf(float x) {
    unsigned r;
    asm("cvt.rna.tf32.f32 %0, %1;" : "=r"(r) : "f"(x));
    return r;
}

__device__ __forceinline__ void mma_tf32(float c[4], const unsigned a[4],
                                         unsigned b0, unsigned b1) {
    asm volatile(
        "mma.sync.aligned.m16n8k8.row.col.f32.tf32.tf32.f32 "
        "{%0,%1,%2,%3}, {%4,%5,%6,%7}, {%8,%9}, {%0,%1,%2,%3};\n"
        : "+f"(c[0]), "+f"(c[1]), "+f"(c[2]), "+f"(c[3])
        : "r"(a[0]), "r"(a[1]), "r"(a[2]), "r"(a[3]), "r"(b0), "r"(b1));
}

// ================= SETUP: wprep + CSR build (one kernel, 104x1024) =================
#define SETUP_NB 104

__global__ __launch_bounds__(1024)
void k_setup(const int* __restrict__ ei,
             const float* __restrict__ W1, const float* __restrict__ W2,
             const float* __restrict__ Wg, float* __restrict__ wfrag,
             int* __restrict__ hist, int* __restrict__ hist2,
             int* __restrict__ rp, int* __restrict__ rp2,
             int* __restrict__ cur, int* __restrict__ cur2,
             int* __restrict__ cse, int2* __restrict__ cde,
             int* __restrict__ bsum, int* __restrict__ bsum2,
             float* __restrict__ dinv) {
    __shared__ int wsum[32];
    int bid = blockIdx.x, tid = threadIdx.x;

    // ---- P0: zero hists (blocks 0..39) | weight prep (blocks 80..103) ----
    if (bid < 40) {
        int i = bid * 1024 + tid;
        if (i < NN) { hist[i] = 0; hist2[i] = 0; }
    } else if (bid >= 80) {
        int idx = (bid - 80) * 1024 + tid;     // 0..24575 = 3*8192
        if (idx < 3 * 8192) {
            int mat = idx >> 13;
            int f   = idx & 8191;
            const float* W = (mat == 0) ? W1 : ((mat == 1) ? W2 : Wg);
            int lane = f & 31, t = (f >> 5) & 15, kk = f >> 9;
            int tig = lane & 3, grp = lane >> 2;
            int colN = t * 8 + grp;
            float x0 = W[(kk * 8 + tig) * C + colN];
            float x1 = W[(kk * 8 + tig + 4) * C + colN];
            float* whi = wfrag + (size_t)mat * 32768;
            float* wlo = whi + 16384;
            unsigned h0 = f2tf(x0); float l0 = x0 - __uint_as_float(h0);
            unsigned h1 = f2tf(x1); float l1 = x1 - __uint_as_float(h1);
            whi[f * 2]     = __uint_as_float(h0);
            whi[f * 2 + 1] = __uint_as_float(h1);
            wlo[f * 2]     = __uint_as_float(f2tf(l0));
            wlo[f * 2 + 1] = __uint_as_float(f2tf(l1));
        }
    }
    gbar(0, SETUP_NB);

    // ---- P1: histogram (all blocks, grid-stride) ----
    for (int e = bid * 1024 + tid; e < ET; e += SETUP_NB * 1024) {
        int s, d;
        if (e < NE) { s = ei[e]; d = ei[NE + e]; }
        else        { s = d = e - NE; }
        atomicAdd(&hist[d], 1);
        atomicAdd(&hist2[s], 1);
    }
    gbar(0, SETUP_NB);

    // ---- P2: block-local scans (blocks 0..79), dinv on dir0 ----
    if (bid < 80) {
        int dir = (bid >= 40);
        int blk = bid - dir * 40;
        const int* in = dir ? hist2 : hist;
        int* rpo = dir ? rp2 : rp;
        int* bso = dir ? bsum2 : bsum;
        int i = blk * 1024 + tid;
        int v = (i < NN) ? in[i] : 0;
        if (!dir && i < NN) dinv[i] = rsqrtf((float)v);   // deg >= 1 (self loop)
        int lane = tid & 31, w = tid >> 5;
        int inc = v;
#pragma unroll
        for (int off = 1; off < 32; off <<= 1) {
            int t = __shfl_up_sync(0xffffffffu, inc, off);
            if (lane >= off) inc += t;
        }
        if (lane == 31) wsum[w] = inc;
        __syncthreads();
        if (w == 0) {
            int xv = wsum[lane];
#pragma unroll
            for (int off = 1; off < 32; off <<= 1) {
                int t = __shfl_up_sync(0xffffffffu, xv, off);
                if (lane >= off) xv += t;
            }
            wsum[lane] = xv;
        }
        __syncthreads();
        int wpre = (w > 0) ? wsum[w - 1] : 0;
        if (i < NN) rpo[i] = wpre + inc - v;
        if (tid == 1023) bso[blk] = wpre + inc;
    } else {
        __syncthreads();    // match the two __syncthreads inside the scan branch
        __syncthreads();
    }
    gbar(0, SETUP_NB);

    // ---- P3: scan of 40 block sums per dir (block 0, warps 0/1, warp-sync only) ----
    if (bid == 0 && tid < 64) {
        int dir = tid >> 5, lane = tid & 31;
        int* bs = dir ? bsum2 : bsum;
        int carry = 0;
        for (int base = 0; base < 40; base += 32) {
            int idx = base + lane;
            int v = (idx < 40) ? bs[idx] : 0;
            int inc = v;
#pragma unroll
            for (int off = 1; off < 32; off <<= 1) {
                int t = __shfl_up_sync(0xffffffffu, inc, off);
                if (lane >= off) inc += t;
            }
            if (idx < 40) bs[idx] = inc - v + carry;   // exclusive + carry
            carry += __shfl_sync(0xffffffffu, inc, 31);
        }
    }
    gbar(0, SETUP_NB);

    // ---- P4: add block offsets -> rp, cur (blocks 0..79) ----
    if (bid < 80) {
        int dir = (bid >= 40);
        int blk = bid - dir * 40;
        int* rpo  = dir ? rp2  : rp;
        int* curo = dir ? cur2 : cur;
        const int* bso = dir ? bsum2 : bsum;
        int i = blk * 1024 + tid;
        if (i < NN) {
            int r = rpo[i] + bso[blk];
            rpo[i]  = r;
            curo[i] = r;
        }
        if (blk == 0 && tid == 0) rpo[NN] = ET;
    }
    gbar(0, SETUP_NB);

    // ---- P5: fill CSR (all blocks, grid-stride) ----
    for (int e = bid * 1024 + tid; e < ET; e += SETUP_NB * 1024) {
        int s, d;
        if (e < NE) { s = ei[e]; d = ei[NE + e]; }
        else        { s = d = e - NE; }
        int pos = atomicAdd(&cur[d], 1);
        cse[pos] = s;
        int pos2 = atomicAdd(&cur2[s], 1);
        cde[pos2] = make_int2(d, pos);
    }
}

// ---------------- GEMM + fused rowdot; fp16 H output ----------------
// BM=64, BN=128, K=128. 8 warps: 2(m) x 4(n), warp tile 32x32.
#define GEMM_SMEM_FLOATS (64 * 132 * 2 + 32768)
#define GEMM_SMEM_BYTES  (GEMM_SMEM_FLOATS * 4)

__global__ __launch_bounds__(256)
void k_gemm_tc(const float* __restrict__ X, const float* __restrict__ wfrag,
               const float* __restrict__ Bb, const float* __restrict__ att,
               __half2* __restrict__ Hh, float* __restrict__ sOut,
               int relu_in, int has_bias) {
    extern __shared__ float smf[];
    float* Xh = smf;                     // [64][132] tf32-hi
    float* Xl = smf + 64 * 132;          // [64][132] tf32-lo
    float* Wh = smf + 2 * 64 * 132;      // [16384] frag-ordered
    float* Wl = Wh + 16384;

    int tid  = threadIdx.x;
    int row0 = blockIdx.x * 64;

    const float4* xg = (const float4*)(X + (size_t)row0 * C);
#pragma unroll
    for (int i = 0; i < 8; i++) {
        int idx = tid + i * 256;
        float4 v = xg[idx];
        if (relu_in) {
            v.x = fmaxf(v.x, 0.f); v.y = fmaxf(v.y, 0.f);
            v.z = fmaxf(v.z, 0.f); v.w = fmaxf(v.w, 0.f);
        }
        int r  = idx >> 5;
        int c0 = (idx & 31) * 4;
        float xv[4] = {v.x, v.y, v.z, v.w};
#pragma unroll
        for (int j = 0; j < 4; j++) {
            unsigned hi = f2tf(xv[j]);
            float lo = xv[j] - __uint_as_float(hi);
            Xh[r * 132 + c0 + j] = __uint_as_float(hi);
            Xl[r * 132 + c0 + j] = __uint_as_float(f2tf(lo));
        }
    }
    {
        const float4* wg = (const float4*)wfrag;
        float4* ws = (float4*)Wh;
#pragma unroll
        for (int i = tid; i < 8192; i += 256) ws[i] = wg[i];
    }
    __syncthreads();

    int wid = tid >> 5, lane = tid & 31;
    int mw = wid & 1, nw = wid >> 1;
    int m0  = mw * 32;
    int n0g = nw * 4;
    int grp = lane >> 2, tig = lane & 3;

    float acc[2][4][4];
#pragma unroll
    for (int ms = 0; ms < 2; ms++)
#pragma unroll
        for (int t = 0; t < 4; t++)
#pragma unroll
            for (int j = 0; j < 4; j++) acc[ms][t][j] = 0.f;

#pragma unroll
    for (int kk = 0; kk < 16; kk++) {
        unsigned ah[2][4], al[2][4];
#pragma unroll
        for (int ms = 0; ms < 2; ms++) {
            int ar = m0 + ms * 16 + grp;
            int ac = kk * 8 + tig;
            ah[ms][0] = __float_as_uint(Xh[ar * 132 + ac]);
            ah[ms][1] = __float_as_uint(Xh[(ar + 8) * 132 + ac]);
            ah[ms][2] = __float_as_uint(Xh[ar * 132 + ac + 4]);
            ah[ms][3] = __float_as_uint(Xh[(ar + 8) * 132 + ac + 4]);
            al[ms][0] = __float_as_uint(Xl[ar * 132 + ac]);
            al[ms][1] = __float_as_uint(Xl[(ar + 8) * 132 + ac]);
            al[ms][2] = __float_as_uint(Xl[ar * 132 + ac + 4]);
            al[ms][3] = __float_as_uint(Xl[(ar + 8) * 132 + ac + 4]);
        }
#pragma unroll
        for (int t = 0; t < 4; t++) {
            int f = (kk * 16 + n0g + t) * 32 + lane;
            uint2 bh = *(const uint2*)(Wh + f * 2);
            uint2 bl = *(const uint2*)(Wl + f * 2);
#pragma unroll
            for (int ms = 0; ms < 2; ms++) {
                mma_tf32(acc[ms][t], ah[ms], bh.x, bh.y);
                mma_tf32(acc[ms][t], al[ms], bh.x, bh.y);
                mma_tf32(acc[ms][t], ah[ms], bl.x, bl.y);
            }
        }
    }

    float part[4] = {0.f, 0.f, 0.f, 0.f};
    bool do_dot = (att != 0);
#pragma unroll
    for (int t = 0; t < 4; t++) {
        int col = (n0g + t) * 8 + tig * 2;
        float2 bv = make_float2(0.f, 0.f);
        if (has_bias) bv = *(const float2*)(Bb + col);
        float2 av = make_float2(0.f, 0.f);
        if (do_dot) av = __ldg((const float2*)(att + col));
#pragma unroll
        for (int ms = 0; ms < 2; ms++) {
            int row = row0 + m0 + ms * 16 + grp;
            float o0 = acc[ms][t][0] + bv.x, o1 = acc[ms][t][1] + bv.y;
            float o2 = acc[ms][t][2] + bv.x, o3 = acc[ms][t][3] + bv.y;
            Hh[(size_t)row * 64 + (col >> 1)]       = __floats2half2_rn(o0, o1);
            Hh[(size_t)(row + 8) * 64 + (col >> 1)] = __floats2half2_rn(o2, o3);
            part[ms * 2]     += o0 * av.x + o1 * av.y;
            part[ms * 2 + 1] += o2 * av.x + o3 * av.y;
        }
    }
    if (do_dot) {
        __syncthreads();
        float* sarr = smf;
        if (tid < 64) sarr[tid] = 0.f;
        __syncthreads();
        atomicAdd(&sarr[m0 + grp],      part[0]);
        atomicAdd(&sarr[m0 + grp + 8],  part[1]);
        atomicAdd(&sarr[m0 + grp + 16], part[2]);
        atomicAdd(&sarr[m0 + grp + 24], part[3]);
        __syncthreads();
        if (tid < 64) sOut[row0 + tid] = sarr[tid];
    }
}

// ================= EDGE: softmax + GT aggregation (one kernel, 296x256) =============
#define EDGE_NB 296
#define EDGE_NW (EDGE_NB * 8)

__global__ __launch_bounds__(256, 2)
void k_edge(const int* __restrict__ rp2, const int2* __restrict__ cde,
            const float* __restrict__ s, float* __restrict__ alpha,
            const int* __restrict__ rp, const int* __restrict__ cse,
            const __half2* __restrict__ Hh, float* __restrict__ out) {
    int gw   = blockIdx.x * 8 + (threadIdx.x >> 5);
    int lane = threadIdx.x & 31;

    // ---- softmax over src groups ----
    for (int node = gw; node < NN; node += EDGE_NW) {
        int beg = rp2[node], end = rp2[node + 1];
        int deg = end - beg;
        float sv = s[node];
        if (deg <= 128) {
            float ex[4];
            int   slot[4];
            int k = 0;
            float mx = -INFINITY;
            for (int p = beg + lane; p < end; p += 32, k++) {
                int2 de = __ldg(&cde[p]);
                float a = sv + __ldg(&s[de.x]);
                a = (a >= 0.f) ? a : 0.2f * a;
                ex[k] = a; slot[k] = de.y;
                mx = fmaxf(mx, a);
            }
#pragma unroll
            for (int o = 16; o > 0; o >>= 1) mx = fmaxf(mx, __shfl_xor_sync(0xffffffffu, mx, o));
            float sum = 0.f;
#pragma unroll
            for (int i = 0; i < 4; i++)
                if (i < k) { ex[i] = expf(ex[i] - mx); sum += ex[i]; }
#pragma unroll
            for (int o = 16; o > 0; o >>= 1) sum += __shfl_xor_sync(0xffffffffu, sum, o);
            float inv = 1.f / (sum + EPS);
#pragma unroll
            for (int i = 0; i < 4; i++)
                if (i < k) alpha[slot[i]] = ex[i] * inv;
        } else {
            float mx = -INFINITY;
            for (int p = beg + lane; p < end; p += 32) {
                int2 de = cde[p];
                float a = sv + s[de.x];
                a = (a >= 0.f) ? a : 0.2f * a;
                mx = fmaxf(mx, a);
            }
#pragma unroll
            for (int o = 16; o > 0; o >>= 1) mx = fmaxf(mx, __shfl_xor_sync(0xffffffffu, mx, o));
            float sum = 0.f;
            for (int p = beg + lane; p < end; p += 32) {
                int2 de = cde[p];
                float a = sv + s[de.x];
                a = (a >= 0.f) ? a : 0.2f * a;
                sum += expf(a - mx);
            }
#pragma unroll
            for (int o = 16; o > 0; o >>= 1) sum += __shfl_xor_sync(0xffffffffu, sum, o);
            float inv = 1.f / (sum + EPS);
            for (int p = beg + lane; p < end; p += 32) {
                int2 de = cde[p];
                float a = sv + s[de.x];
                a = (a >= 0.f) ? a : 0.2f * a;
                alpha[de.y] = expf(a - mx) * inv;
            }
        }
    }

    gbar(1, EDGE_NB);

    // ---- GT aggregation (gather) ----
    for (int node = gw; node < NN; node += EDGE_NW) {
        int beg = rp[node], end = rp[node + 1];
        float ax = 0.f, ay = 0.f, az = 0.f, aw = 0.f;
        if (beg < end) {
            int   sn = __ldg(&cse[beg]);
            float w  = __ldg(&alpha[beg]);
            for (int p = beg; p < end; p++) {
                int sn_n = 0; float w_n = 0.f;
                if (p + 1 < end) {
                    sn_n = __ldg(&cse[p + 1]);
                    w_n  = __ldg(&alpha[p + 1]);
                }
                uint2 u = __ldg((const uint2*)(Hh + (size_t)sn * 64) + lane);
                float2 f0 = __half22float2(*(const __half2*)&u.x);
                float2 f1 = __half22float2(*(const __half2*)&u.y);
                ax = fmaf(w, f0.x, ax); ay = fmaf(w, f0.y, ay);
                az = fmaf(w, f1.x, az); aw = fmaf(w, f1.y, aw);
                sn = sn_n; w = w_n;
            }
        }
        *(float4*)(out + (size_t)node * C + lane * 4) = make_float4(ax, ay, az, aw);
    }
}

// ================= TAIL: GCN agg + mean pool + head (one kernel, 296x256) ===========
#define TAIL_NB 296
#define TAIL_NW (TAIL_NB * 8)
#define TAIL_NHB (TAIL_NB * 2)

__global__ __launch_bounds__(256, 2)
void k_tail(const __half2* __restrict__ Hh, const int* __restrict__ rp,
            const int* __restrict__ cse, const float* __restrict__ dinv,
            float* __restrict__ t1, const int* __restrict__ batch,
            float* __restrict__ pool, float* __restrict__ cnt,
            const float* __restrict__ bg, const float* __restrict__ Wfc,
            const float* __restrict__ bfc, float* __restrict__ out) {
    int gtid = blockIdx.x * 256 + threadIdx.x;
    int gw   = gtid >> 5;
    int lane = threadIdx.x & 31;

    // zero pool/cnt (visible after the barrier below)
    if (gtid < NG * C) pool[gtid] = 0.f;
    if (gtid < NG) cnt[gtid] = 0.f;

    // ---- GCN aggregation ----
    for (int node = gw; node < NN; node += TAIL_NW) {
        int beg = rp[node], end = rp[node + 1];
        float dd = dinv[node];
        float ax = 0.f, ay = 0.f, az = 0.f, aw = 0.f;
        if (beg < end) {
            int   sn = __ldg(&cse[beg]);
            float w  = dd * __ldg(&dinv[sn]);
            for (int p = beg; p < end; p++) {
                int sn_n = 0; float w_n = 0.f;
                if (p + 1 < end) {
                    sn_n = __ldg(&cse[p + 1]);
                    w_n  = dd * __ldg(&dinv[sn_n]);
                }
                uint2 u = __ldg((const uint2*)(Hh + (size_t)sn * 64) + lane);
                float2 f0 = __half22float2(*(const __half2*)&u.x);
                float2 f1 = __half22float2(*(const __half2*)&u.y);
                ax = fmaf(w, f0.x, ax); ay = fmaf(w, f0.y, ay);
                az = fmaf(w, f1.x, az); aw = fmaf(w, f1.y, aw);
                sn = sn_n; w = w_n;
            }
        }
        *(float4*)(t1 + (size_t)node * C + lane * 4) = make_float4(ax, ay, az, aw);
    }

    gbar(2, TAIL_NB);

    // ---- mean pool (half-block = 128-channel worker over a contiguous node range) ----
    {
        int hb = blockIdx.x * 2 + (threadIdx.x >> 7);   // 0..591
        int c  = threadIdx.x & 127;
        int per = (NN + TAIL_NHB - 1) / TAIL_NHB;       // 68
        int n0 = hb * per;
        int n1 = n0 + per; if (n1 > NN) n1 = NN;
        if (n0 < n1) {
            float acc = 0.f;
            int cc = 0;
            int curg = batch[n0];
            for (int i = n0; i < n1; i++) {
                int g = batch[i];
                if (g != curg) {
                    atomicAdd(&pool[(size_t)curg * C + c], acc);
                    if (c == 0) atomicAdd(&cnt[curg], (float)cc);
                    acc = 0.f; cc = 0; curg = g;
                }
                acc += t1[(size_t)i * C + c];
                cc++;
            }
            atomicAdd(&pool[(size_t)curg * C + c], acc);
            if (c == 0) atomicAdd(&cnt[curg], (float)cc);
        }
    }

    gbar(2, TAIL_NB);

    // ---- head: warp per graph (global warps 0..63) ----
    if (gw < NG) {
        int g = gw;
        float cg = fmaxf(cnt[g], 1.f);
        float logit = -INFINITY;
        if (lane < OC) {
            float acc = 0.f;
            for (int c = 0; c < C; c++) {
                float p = pool[(size_t)g * C + c] / cg + bg[c];
                acc = fmaf(p, Wfc[c * OC + lane], acc);
            }
            logit = acc + bfc[lane];
        }
        float mx = logit;
#pragma unroll
        for (int o = 16; o > 0; o >>= 1) mx = fmaxf(mx, __shfl_xor_sync(0xffffffffu, mx, o));
        float ex = (lane < OC) ? expf(logit - mx) : 0.f;
        float sm = ex;
#pragma unroll
        for (int o = 16; o > 0; o >>= 1) sm += __shfl_xor_sync(0xffffffffu, sm, o);
        if (lane < OC) out[g * OC + lane] = logit - mx - logf(sm);
    }
}

// ---------------- host orchestration ----------------
extern "C" void kernel_launch(void* const* d_in, const int* in_sizes, int n_in,
                              void* d_out, int out_size) {
    const float* x    = (const float*)d_in[0];
    const int*   ei   = (const int*)  d_in[1];
    const int*   batch= (const int*)  d_in[2];
    const float* W1   = (const float*)d_in[3];
    const float* b1   = (const float*)d_in[4];
    const float* att1 = (const float*)d_in[5];
    const float* W2   = (const float*)d_in[6];
    const float* b2   = (const float*)d_in[7];
    const float* att2 = (const float*)d_in[8];
    const float* Wg   = (const float*)d_in[9];
    const float* bg   = (const float*)d_in[10];
    const float* Wfc  = (const float*)d_in[11];
    const float* bfc  = (const float*)d_in[12];
    float* out = (float*)d_out;

    void *phh, *pt1, *pt2, *ps, *pal, *pdi, *phist, *phist2, *prp, *prp2,
         *pcur, *pcur2, *pcse, *pcde, *pbs, *pbs2, *ppool, *pcnt, *pwf;
    cudaGetSymbolAddress(&phh,   g_hh);
    cudaGetSymbolAddress(&pt1,   g_t1);
    cudaGetSymbolAddress(&pt2,   g_t2);
    cudaGetSymbolAddress(&ps,    g_s);
    cudaGetSymbolAddress(&pal,   g_alpha);
    cudaGetSymbolAddress(&pdi,   g_dinv);
    cudaGetSymbolAddress(&phist, g_hist);
    cudaGetSymbolAddress(&phist2,g_hist2);
    cudaGetSymbolAddress(&prp,   g_rp);
    cudaGetSymbolAddress(&prp2,  g_rp2);
    cudaGetSymbolAddress(&pcur,  g_cur);
    cudaGetSymbolAddress(&pcur2, g_cur2);
    cudaGetSymbolAddress(&pcse,  g_cse);
    cudaGetSymbolAddress(&pcde,  g_cde);
    cudaGetSymbolAddress(&pbs,   g_bsum);
    cudaGetSymbolAddress(&pbs2,  g_bsum2);
    cudaGetSymbolAddress(&ppool, g_pool);
    cudaGetSymbolAddress(&pcnt,  g_cnt);
    cudaGetSymbolAddress(&pwf,   g_wfrag);

    __half2* hh  = (__half2*)phh;
    float* t1    = (float*)pt1;   float* t2   = (float*)pt2;
    float* s     = (float*)ps;    float* alpha = (float*)pal;
    float* dinv  = (float*)pdi;   int* hist   = (int*)phist;
    int* hist2   = (int*)phist2;  int* rp     = (int*)prp;
    int* rp2     = (int*)prp2;    int* cur    = (int*)pcur;
    int* cur2    = (int*)pcur2;   int* cse    = (int*)pcse;
    int2* cde    = (int2*)pcde;   int* bsum   = (int*)pbs;
    int* bsum2   = (int*)pbs2;    float* pool = (float*)ppool;
    float* cnt   = (float*)pcnt;  float* wfrag = (float*)pwf;

    cudaFuncSetAttribute(k_gemm_tc, cudaFuncAttributeMaxDynamicSharedMemorySize,
                         GEMM_SMEM_BYTES);

    const int NBG = NN / 64;    // 625 GEMM blocks

    // ---- setup: wprep + CSR build (one fused kernel) ----
    k_setup<<<SETUP_NB, 1024>>>(ei, W1, W2, Wg, wfrag, hist, hist2, rp, rp2,
                                cur, cur2, cse, cde, bsum, bsum2, dinv);

    // ---- GT layer 1 ----
    k_gemm_tc<<<NBG, 256, GEMM_SMEM_BYTES>>>(x, wfrag, b1, att1, hh, s, 0, 1);
    k_edge<<<EDGE_NB, 256>>>(rp2, cde, s, alpha, rp, cse, hh, t1);

    // ---- GT layer 2 ----
    k_gemm_tc<<<NBG, 256, GEMM_SMEM_BYTES>>>(t1, wfrag + 32768, b2, att2, hh, s, 1, 1);
    k_edge<<<EDGE_NB, 256>>>(rp2, cde, s, alpha, rp, cse, hh, t2);

    // ---- GCN layer + pool + head ----
    k_gemm_tc<<<NBG, 256, GEMM_SMEM_BYTES>>>(t2, wfrag + 65536, (const float*)0,
                                             (const float*)0, hh, s, 1, 0);
    k_tail<<<TAIL_NB, 256>>>(hh, rp, cse, dinv, t1, batch, pool, cnt,
                             bg, Wfc, bfc, out);
}